// round 17
// baseline (speedup 1.0000x reference)
#include <cuda_runtime.h>
#include <cuda_bf16.h>
#include <cuda_fp16.h>
#include <cstdint>

#define HID   768
#define HID3  2304
#define SEQ   2048
#define BATCH 8
#define TOK   (BATCH * SEQ)

#define BM 128
#define BN 256
#define BK 64                 // 16-bit elems per chunk = 128 B/row
#define NTHREADS 512
#define NSTAGE 3
#define A_BYTES 16384         // 128 rows x 128 B
#define B_BYTES 32768         // 256 rows x 128 B
#define STAGE_BYTES (A_BYTES + B_BYTES)          // 48 KB
#define SM_TOTAL (NSTAGE * STAGE_BYTES)          // 144 KB -> 1 CTA x 512 thr = 16 warps/SM

// ---------------- scratch (__device__ globals, allocation-free rule) ----------------
__device__ __align__(1024) __nv_bfloat16 g_x_hi[(size_t)TOK * HID];
__device__ __align__(1024) __nv_bfloat16 g_x_lo[(size_t)TOK * HID];
__device__ __align__(1024) __half        g_x_f16[(size_t)TOK * HID];
__device__ __align__(1024) __nv_bfloat16 g_w_hi[(size_t)HID3 * HID];
__device__ __align__(1024) __nv_bfloat16 g_w_lo[(size_t)HID3 * HID];
__device__ __align__(1024) __half        g_wv_f16[(size_t)HID * HID];        // W rows [2H,3H)
__device__ __align__(1024) __nv_bfloat16 g_q_hi[(size_t)TOK * HID];
__device__ __align__(1024) __nv_bfloat16 g_q_lo[(size_t)TOK * HID];
__device__ __align__(1024) __nv_bfloat16 g_k_hi[(size_t)TOK * HID];
__device__ __align__(1024) __nv_bfloat16 g_k_lo[(size_t)TOK * HID];
__device__ __align__(1024) __half        g_vT[(size_t)BATCH * HID * SEQ];    // [b][dim][tok]
__device__ __align__(1024) float         g_S[(size_t)BATCH * SEQ * SEQ];
__device__ __align__(1024) __half        g_P[(size_t)TOK * SEQ];

// ---------------- PTX helpers (sm_80-era only: legal on plain sm_103) ----------------
__device__ __forceinline__ uint32_t smem_u32(const void* p) {
    uint32_t a;
    asm("{ .reg .u64 t; cvta.to.shared.u64 t, %1; cvt.u32.u64 %0, t; }" : "=r"(a) : "l"(p));
    return a;
}
__device__ __forceinline__ void cp16(uint32_t dst, const void* src) {
    asm volatile("cp.async.cg.shared.global [%0], [%1], 16;"
                 :: "r"(dst), "l"(__cvta_generic_to_global(src)) : "memory");
}
#define CP_COMMIT() asm volatile("cp.async.commit_group;" ::: "memory")
#define CP_WAIT1()  asm volatile("cp.async.wait_group 1;" ::: "memory")

__device__ __forceinline__ void ldsm_x4(uint32_t& d0, uint32_t& d1, uint32_t& d2,
                                        uint32_t& d3, uint32_t addr) {
    asm volatile("ldmatrix.sync.aligned.m8n8.x4.shared.b16 {%0,%1,%2,%3}, [%4];"
                 : "=r"(d0), "=r"(d1), "=r"(d2), "=r"(d3) : "r"(addr));
}
template <bool FP16>
__device__ __forceinline__ void mma16816(float (&c)[4], uint32_t a0, uint32_t a1,
                                         uint32_t a2, uint32_t a3,
                                         uint32_t b0, uint32_t b1) {
    if (FP16)
        asm volatile("mma.sync.aligned.m16n8k16.row.col.f32.f16.f16.f32 "
                     "{%0,%1,%2,%3}, {%4,%5,%6,%7}, {%8,%9}, {%0,%1,%2,%3};"
                     : "+f"(c[0]), "+f"(c[1]), "+f"(c[2]), "+f"(c[3])
                     : "r"(a0), "r"(a1), "r"(a2), "r"(a3), "r"(b0), "r"(b1));
    else
        asm volatile("mma.sync.aligned.m16n8k16.row.col.f32.bf16.bf16.f32 "
                     "{%0,%1,%2,%3}, {%4,%5,%6,%7}, {%8,%9}, {%0,%1,%2,%3};"
                     : "+f"(c[0]), "+f"(c[1]), "+f"(c[2]), "+f"(c[3])
                     : "r"(a0), "r"(a1), "r"(a2), "r"(a3), "r"(b0), "r"(b1));
}

__device__ __forceinline__ void split1(float v, __nv_bfloat16& h, __nv_bfloat16& l) {
    h = __float2bfloat16(v);
    l = __float2bfloat16(v - __bfloat162float(h));
}

// ---------------------------------------------------------------------------
// Split-GEMM HMMA mainloop. 512 threads, 16 warps (4x4), warp tile 32x64,
// CTA tile 128x256. 3-stage cp.async (wait_group 1). Strength-reduced issue:
// per-thread offsets hoisted, chunk/combo tracked incrementally (no div/mod).
//   NCOMBO=3 (bf16x3): (A0,B0),(A1,B0),(A0,B1)   NCOMBO=1: (A0,B0) only.
// ---------------------------------------------------------------------------
template <int NCOMBO, bool FP16>
__device__ __forceinline__ void run_mainloop(
    const uint8_t* __restrict__ A0, const uint8_t* __restrict__ A1, int lda,
    const uint8_t* __restrict__ B0, const uint8_t* __restrict__ B1, int ldb,
    int K, int row0, int bcol0, char* smem, float (&acc)[2][8][4])
{
    const int tid  = threadIdx.x;
    const int lane = tid & 31, wid = tid >> 5;
    const int warp_m = wid >> 2, warp_n = wid & 3;
    const uint32_t sb = smem_u32(smem);

#pragma unroll
    for (int mt = 0; mt < 2; mt++)
#pragma unroll
        for (int nt = 0; nt < 8; nt++)
#pragma unroll
            for (int j = 0; j < 4; j++) acc[mt][nt][j] = 0.f;

    const int NIT = NCOMBO * (K / BK);

    // hoisted per-thread cp.async offsets
    uint32_t dstA[2]; size_t srcA[2];
#pragma unroll
    for (int w = 0; w < 2; w++) {
        int idx = tid + w * NTHREADS, r = idx >> 3, c8 = idx & 7;
        dstA[w] = (uint32_t)(r * 128 + ((c8 ^ (r & 7)) << 4));
        srcA[w] = (size_t)(row0 + r) * lda * 2 + c8 * 16;
    }
    uint32_t dstB[4]; size_t srcB[4];
#pragma unroll
    for (int w = 0; w < 4; w++) {
        int idx = tid + w * NTHREADS, r = idx >> 3, c8 = idx & 7;
        dstB[w] = (uint32_t)(A_BYTES + r * 128 + ((c8 ^ (r & 7)) << 4));
        srcB[w] = (size_t)(bcol0 + r) * ldb * 2 + c8 * 16;
    }

    int ic = 0, cc = 0;        // issue-side chunk / combo counters
    auto issue = [&](uint32_t stg) {
        const uint8_t* A = (NCOMBO == 3 && cc == 1) ? A1 : A0;
        const uint8_t* B = (NCOMBO >= 2 && cc == NCOMBO - 1) ? B1 : B0;
        const size_t k0b = (size_t)ic * (BK * 2);
        const uint32_t st = sb + stg * STAGE_BYTES;
#pragma unroll
        for (int w = 0; w < 2; w++) cp16(st + dstA[w], A + srcA[w] + k0b);
#pragma unroll
        for (int w = 0; w < 4; w++) cp16(st + dstB[w], B + srcB[w] + k0b);
        if (++cc == NCOMBO) { cc = 0; ++ic; }
    };

    issue(0); CP_COMMIT();
    issue(1); CP_COMMIT();

    // per-thread ldmatrix address invariants
    const int rowA = warp_m * 32 + (lane & 15);     // + mt*16 (keeps r&7)
    const int hA   = lane >> 4, sA7 = rowA & 7;
    const int rB   = warp_n * 64 + (lane & 7) + ((lane >> 4) << 3);  // + p*16
    const int hB   = (lane >> 3) & 1, sB7 = lane & 7;

    int sCur = 0, sNxt = 2;
    for (int it = 0; it < NIT; it++) {
        CP_WAIT1();
        __syncthreads();
        if (it + 2 < NIT) issue((uint32_t)sNxt);
        CP_COMMIT();

        const uint32_t sA  = sb + (uint32_t)sCur * STAGE_BYTES;
        const uint32_t sBs = sA + A_BYTES;
#pragma unroll
        for (int k16 = 0; k16 < 4; k16++) {
            uint32_t a[2][4], b[4][4];
#pragma unroll
            for (int mt = 0; mt < 2; mt++)
                ldsm_x4(a[mt][0], a[mt][1], a[mt][2], a[mt][3],
                        sA + (rowA + mt * 16) * 128 + (((k16 * 2 + hA) ^ sA7) << 4));
#pragma unroll
            for (int p = 0; p < 4; p++)
                ldsm_x4(b[p][0], b[p][1], b[p][2], b[p][3],
                        sBs + (rB + p * 16) * 128 + (((k16 * 2 + hB) ^ sB7) << 4));
#pragma unroll
            for (int mt = 0; mt < 2; mt++)
#pragma unroll
                for (int nt = 0; nt < 8; nt++)
                    mma16816<FP16>(acc[mt][nt], a[mt][0], a[mt][1], a[mt][2], a[mt][3],
                                   b[nt >> 1][(nt & 1) * 2], b[nt >> 1][(nt & 1) * 2 + 1]);
        }
        if (++sCur == NSTAGE) sCur = 0;
        if (++sNxt == NSTAGE) sNxt = 0;
    }
}

// ---------------- stage 0a: x -> bf16 hi/lo + fp16 ----------------
__global__ __launch_bounds__(256) void split_x_kernel(
    const float* __restrict__ src, int n4)
{
    int i = blockIdx.x * 256 + threadIdx.x;
    if (i >= n4) return;
    float4 v = ((const float4*)src)[i];
    __nv_bfloat16 h0, l0, h1, l1, h2, l2, h3, l3;
    split1(v.x, h0, l0); split1(v.y, h1, l1);
    split1(v.z, h2, l2); split1(v.w, h3, l3);
    __nv_bfloat162* H = (__nv_bfloat162*)g_x_hi;
    __nv_bfloat162* L = (__nv_bfloat162*)g_x_lo;
    H[2 * i]     = __nv_bfloat162(h0, h1);
    H[2 * i + 1] = __nv_bfloat162(h2, h3);
    L[2 * i]     = __nv_bfloat162(l0, l1);
    L[2 * i + 1] = __nv_bfloat162(l2, l3);
    __half2* F = (__half2*)g_x_f16;
    F[2 * i]     = __floats2half2_rn(v.x, v.y);
    F[2 * i + 1] = __floats2half2_rn(v.z, v.w);
}

// ---------------- stage 0b: W -> bf16 hi/lo (q/k rows) + fp16 (v rows) ----------------
__global__ __launch_bounds__(256) void split_w_kernel(
    const float* __restrict__ W, int n4)
{
    int i = blockIdx.x * 256 + threadIdx.x;
    if (i >= n4) return;
    float4 v = ((const float4*)W)[i];
    __nv_bfloat16 h0, l0, h1, l1, h2, l2, h3, l3;
    split1(v.x, h0, l0); split1(v.y, h1, l1);
    split1(v.z, h2, l2); split1(v.w, h3, l3);
    __nv_bfloat162* H = (__nv_bfloat162*)g_w_hi;
    __nv_bfloat162* L = (__nv_bfloat162*)g_w_lo;
    H[2 * i]     = __nv_bfloat162(h0, h1);
    H[2 * i + 1] = __nv_bfloat162(h2, h3);
    L[2 * i]     = __nv_bfloat162(l0, l1);
    L[2 * i + 1] = __nv_bfloat162(l2, l3);
    const int vstart4 = 2 * HID * HID / 4;     // first float4 index of v rows
    if (i >= vstart4) {
        __half2* F = (__half2*)g_wv_f16;
        int j = i - vstart4;
        F[2 * j]     = __floats2half2_rn(v.x, v.y);
        F[2 * j + 1] = __floats2half2_rn(v.z, v.w);
    }
}

// ---------------- stage 1: QKV = x @ W^T + b ----------------
// 256-col tiles: 0-2 -> q, 3-5 -> k, 6-8 -> v (boundaries 768/1536 align).
// v tiles: 1-pass fp16, staged in smem, transposed coalesced fp16 vT stores.
#define VT_PITCH 136   // elems; 272 B row pitch (16B aligned, conflict-skewed)

__global__ __launch_bounds__(NTHREADS) void qkv_gemm(const float* __restrict__ bias)
{
    extern __shared__ char smem[];
    const int row0 = blockIdx.y * BM;
    const int col0 = blockIdx.x * BN;
    float acc[2][8][4];

    const int tid = threadIdx.x;
    const int lane = tid & 31, wid = tid >> 5;
    const int warp_m = wid >> 2, warp_n = wid & 3;
    const int quad = lane >> 2, qt = lane & 3;

    if (col0 < 2 * HID) {
        run_mainloop<3, false>((const uint8_t*)g_x_hi, (const uint8_t*)g_x_lo, HID,
                               (const uint8_t*)g_w_hi, (const uint8_t*)g_w_lo, HID,
                               HID, row0, col0, smem, acc);
        __nv_bfloat16* dh = (col0 < HID) ? g_q_hi : g_k_hi;
        __nv_bfloat16* dl = (col0 < HID) ? g_q_lo : g_k_lo;
        const int cbase = (col0 < HID) ? col0 : (col0 - HID);
#pragma unroll
        for (int mt = 0; mt < 2; mt++)
#pragma unroll
            for (int h = 0; h < 2; h++) {
                const int t = row0 + warp_m * 32 + mt * 16 + quad + h * 8;
#pragma unroll
                for (int nt = 0; nt < 8; nt++) {
                    const int lcol = warp_n * 64 + nt * 8 + qt * 2;
                    float v0 = acc[mt][nt][2 * h]     + __ldg(bias + col0 + lcol);
                    float v1 = acc[mt][nt][2 * h + 1] + __ldg(bias + col0 + lcol + 1);
                    __nv_bfloat16 h0, l0, h1, l1;
                    split1(v0, h0, l0); split1(v1, h1, l1);
                    size_t o = (size_t)t * HID + cbase + lcol;
                    *(__nv_bfloat162*)(dh + o) = __nv_bfloat162(h0, h1);
                    *(__nv_bfloat162*)(dl + o) = __nv_bfloat162(l0, l1);
                }
            }
    } else {
        // ---- v tile: 1-pass fp16 GEMM, then transposed coalesced fp16 store ----
        run_mainloop<1, true>((const uint8_t*)g_x_f16, nullptr, HID,
                              (const uint8_t*)g_wv_f16, nullptr, HID,
                              HID, row0, col0 - 2 * HID, smem, acc);
        __syncthreads();    // all warps done reading stage buffers
        __half* sv = (__half*)smem;                          // [256 dims][VT_PITCH]
#pragma unroll
        for (int mt = 0; mt < 2; mt++)
#pragma unroll
            for (int h = 0; h < 2; h++) {
                const int r = warp_m * 32 + mt * 16 + quad + h * 8;   // local token
#pragma unroll
                for (int nt = 0; nt < 8; nt++) {
                    const int lcol = warp_n * 64 + nt * 8 + qt * 2;   // local dim
                    float v0 = acc[mt][nt][2 * h]     + __ldg(bias + col0 + lcol);
                    float v1 = acc[mt][nt][2 * h + 1] + __ldg(bias + col0 + lcol + 1);
                    sv[lcol * VT_PITCH + r]       = __float2half(v0);
                    sv[(lcol + 1) * VT_PITCH + r] = __float2half(v1);
                }
            }
        __syncthreads();
        const int bz = row0 >> 11, tr0 = row0 & 2047;
        const int d0 = col0 - 2 * HID;
        const int d = tid >> 1, half_ = tid & 1;     // 256 dims x 2 64-tok halves
        const size_t go = ((size_t)bz * HID + d0 + d) * SEQ + tr0 + half_ * 64;
        const uint4* s4 = (const uint4*)(sv + d * VT_PITCH + half_ * 64);
        uint4* g4 = (uint4*)(g_vT + go);
#pragma unroll
        for (int u = 0; u < 8; u++) g4[u] = s4[u];
    }
}

// ---------------- stage 2: S = q @ k^T (per batch) ----------------
__global__ __launch_bounds__(NTHREADS) void qk_gemm()
{
    extern __shared__ char smem[];
    const int bz = blockIdx.z;
    const size_t off = (size_t)bz * SEQ * HID;
    const int row0 = blockIdx.y * BM;
    const int col0 = blockIdx.x * BN;
    float acc[2][8][4];
    run_mainloop<3, false>((const uint8_t*)(g_q_hi + off), (const uint8_t*)(g_q_lo + off), HID,
                           (const uint8_t*)(g_k_hi + off), (const uint8_t*)(g_k_lo + off), HID,
                           HID, row0, col0, smem, acc);

    const int lane = threadIdx.x & 31, wid = threadIdx.x >> 5;
    const int warp_m = wid >> 2, warp_n = wid & 3;
    const int quad = lane >> 2, qt = lane & 3;
#pragma unroll
    for (int mt = 0; mt < 2; mt++)
#pragma unroll
        for (int h = 0; h < 2; h++) {
            const int m = row0 + warp_m * 32 + mt * 16 + quad + h * 8;
            float* Srow = g_S + ((size_t)bz * SEQ + m) * SEQ;
#pragma unroll
            for (int nt = 0; nt < 8; nt++) {
                const int c = col0 + warp_n * 64 + nt * 8 + qt * 2;
                float2 v; v.x = acc[mt][nt][2 * h]; v.y = acc[mt][nt][2 * h + 1];
                *(float2*)(Srow + c) = v;
            }
        }
}

// ---------------- stage 3: softmax -> fp16 P ----------------
__global__ __launch_bounds__(256) void softmax_split_kernel()
{
    const size_t row = blockIdx.x;
    const float4* p4 = (const float4*)(g_S + row * SEQ);
    const int tid = threadIdx.x;
    float4 v0 = p4[tid];
    float4 v1 = p4[tid + 256];

    float m = fmaxf(fmaxf(fmaxf(v0.x, v0.y), fmaxf(v0.z, v0.w)),
                    fmaxf(fmaxf(v1.x, v1.y), fmaxf(v1.z, v1.w)));
    __shared__ float red[8], red2[8];
#pragma unroll
    for (int o = 16; o; o >>= 1) m = fmaxf(m, __shfl_xor_sync(0xffffffffu, m, o));
    if ((tid & 31) == 0) red[tid >> 5] = m;
    __syncthreads();
    float bm = red[0];
#pragma unroll
    for (int i = 1; i < 8; i++) bm = fmaxf(bm, red[i]);

    v0.x = __expf(v0.x - bm); v0.y = __expf(v0.y - bm);
    v0.z = __expf(v0.z - bm); v0.w = __expf(v0.w - bm);
    v1.x = __expf(v1.x - bm); v1.y = __expf(v1.y - bm);
    v1.z = __expf(v1.z - bm); v1.w = __expf(v1.w - bm);

    float s = ((v0.x + v0.y) + (v0.z + v0.w)) + ((v1.x + v1.y) + (v1.z + v1.w));
#pragma unroll
    for (int o = 16; o; o >>= 1) s += __shfl_xor_sync(0xffffffffu, s, o);
    if ((tid & 31) == 0) red2[tid >> 5] = s;
    __syncthreads();
    float ts = red2[0];
#pragma unroll
    for (int i = 1; i < 8; i++) ts += red2[i];
    const float inv = 1.0f / ts;

    __half2* P2 = (__half2*)(g_P + row * SEQ);
    P2[2 * tid]     = __floats2half2_rn(v0.x * inv, v0.y * inv);
    P2[2 * tid + 1] = __floats2half2_rn(v0.z * inv, v0.w * inv);
    P2[2 * (tid + 256)]     = __floats2half2_rn(v1.x * inv, v1.y * inv);
    P2[2 * (tid + 256) + 1] = __floats2half2_rn(v1.z * inv, v1.w * inv);
}

// ---------------- stage 4: out = P @ v (single-pass fp16) ----------------
__global__ __launch_bounds__(NTHREADS) void pv_gemm(float* __restrict__ out)
{
    extern __shared__ char smem[];
    const int bz = blockIdx.z;
    const size_t pOff = (size_t)bz * SEQ * SEQ;
    const size_t vOff = (size_t)bz * HID * SEQ;
    const int row0 = blockIdx.y * BM;
    const int col0 = blockIdx.x * BN;
    float acc[2][8][4];
    run_mainloop<1, true>((const uint8_t*)(g_P + pOff), nullptr, SEQ,
                          (const uint8_t*)(g_vT + vOff), nullptr, SEQ,
                          SEQ, row0, col0, smem, acc);

    const int lane = threadIdx.x & 31, wid = threadIdx.x >> 5;
    const int warp_m = wid >> 2, warp_n = wid & 3;
    const int quad = lane >> 2, qt = lane & 3;
#pragma unroll
    for (int mt = 0; mt < 2; mt++)
#pragma unroll
        for (int h = 0; h < 2; h++) {
            const int m = row0 + warp_m * 32 + mt * 16 + quad + h * 8;
            float* Orow = out + ((size_t)bz * SEQ + m) * HID;
#pragma unroll
            for (int nt = 0; nt < 8; nt++) {
                const int c = col0 + warp_n * 64 + nt * 8 + qt * 2;
                float2 v; v.x = acc[mt][nt][2 * h]; v.y = acc[mt][nt][2 * h + 1];
                *(float2*)(Orow + c) = v;
            }
        }
}

// ---------------------------------------------------------------------------
extern "C" void kernel_launch(void* const* d_in, const int* in_sizes, int n_in,
                              void* d_out, int out_size)
{
    const float* x = (const float*)d_in[0];
    const float* W = (const float*)d_in[1];
    const float* b = (const float*)d_in[2];
    float* out = (float*)d_out;
    (void)in_sizes; (void)n_in; (void)out_size;

    cudaFuncSetAttribute(qkv_gemm, cudaFuncAttributeMaxDynamicSharedMemorySize, SM_TOTAL);
    cudaFuncSetAttribute(qk_gemm,  cudaFuncAttributeMaxDynamicSharedMemorySize, SM_TOTAL);
    cudaFuncSetAttribute(pv_gemm,  cudaFuncAttributeMaxDynamicSharedMemorySize, SM_TOTAL);

    int nx4 = TOK * HID / 4, nw4 = HID3 * HID / 4;
    split_x_kernel<<<(nx4 + 255) / 256, 256>>>(x, nx4);
    split_w_kernel<<<(nw4 + 255) / 256, 256>>>(W, nw4);

    qkv_gemm<<<dim3(HID3 / BN, TOK / BM, 1), NTHREADS, SM_TOTAL>>>(b);
    qk_gemm<<<dim3(SEQ / BN, SEQ / BM, BATCH), NTHREADS, SM_TOTAL>>>();
    softmax_split_kernel<<<TOK, 256>>>();
    pv_gemm<<<dim3(HID / BN, SEQ / BM, BATCH), NTHREADS, SM_TOTAL>>>(out);
}